// round 3
// baseline (speedup 1.0000x reference)
#include <cuda_runtime.h>
#include <cstdint>
#include <cstddef>

#define NN_MAX 100000
#define NE_MAX 1600000
#define CH 128

// Scratch (static __device__ allocation is the sanctioned workaround)
__device__ float g_x0[(size_t)NN_MAX * CH];
__device__ float g_x1[(size_t)NN_MAX * CH];
__device__ float g_agg[(size_t)NN_MAX * CH];
__device__ int   g_ei32[(size_t)2 * NE_MAX];
__device__ int   g_is64;

// ---------- f32x2 helpers (sm_103a packed fp32 pipe) ----------
__device__ __forceinline__ unsigned long long pack2(float a, float b) {
    unsigned long long r;
    asm("mov.b64 %0, {%1, %2};" : "=l"(r) : "f"(a), "f"(b));
    return r;
}
__device__ __forceinline__ float2 unpack2(unsigned long long v) {
    float2 f;
    asm("mov.b64 {%0, %1}, %2;" : "=f"(f.x), "=f"(f.y) : "l"(v));
    return f;
}
__device__ __forceinline__ unsigned long long fma2(unsigned long long a,
                                                   unsigned long long b,
                                                   unsigned long long c) {
    unsigned long long d;
    asm("fma.rn.f32x2 %0, %1, %2, %3;" : "=l"(d) : "l"(a), "l"(b), "l"(c));
    return d;
}
__device__ __forceinline__ void red2(float* p, float a, float b) {
    asm volatile("red.global.add.v2.f32 [%0], {%1, %2};"
                 :: "l"(p), "f"(a), "f"(b) : "memory");
}

// ---------- dtype detection + index canonicalization ----------
// If edge_index is int64 (values < 1e5 < 2^31), every odd 32-bit word is 0.
// If int32, odd words are random node ids (all-zero over 128 samples ~ impossible).
// Reads only the first 1 KB, valid under both interpretations.
__global__ void detect_kernel(const unsigned int* e32) {
    if (threadIdx.x == 0 && blockIdx.x == 0) {
        int is64 = 1;
        for (int i = 0; i < 256; i += 2)
            if (e32[i + 1] != 0u) is64 = 0;
        g_is64 = is64;
    }
}

__global__ void convert_kernel(const void* ei, int n2) {
    int f = g_is64;
    int i = blockIdx.x * blockDim.x + threadIdx.x;
    int stride = gridDim.x * blockDim.x;
    if (f) {
        const long long* p = (const long long*)ei;
        for (; i < n2; i += stride) g_ei32[i] = (int)p[i];
    } else {
        const int* p = (const int*)ei;
        for (; i < n2; i += stride) g_ei32[i] = p[i];
    }
}

// ---------- Edge kernel: msg = relu(x[src] + edge_attr@We + be); red-add into agg ----------
// 2 warps per edge; lane handles 2 channels; We slice lives in 64 registers.
__global__ void __launch_bounds__(256) edge_kernel(
    const float* __restrict__ x, const int* __restrict__ srcArr,
    const int* __restrict__ dstArr,
    const float* __restrict__ ea, const float* __restrict__ We,
    const float* __restrict__ be, float* __restrict__ agg, int nEdges)
{
    int lane = threadIdx.x & 31;
    int gw   = blockIdx.x * 8 + (threadIdx.x >> 5);
    int half = gw & 1;
    int c0   = half * 64 + lane * 2;

    unsigned long long wreg[32];
#pragma unroll
    for (int k = 0; k < 32; k++)
        wreg[k] = *(const unsigned long long*)&We[k * 128 + c0];

    float2 bf = *(const float2*)&be[c0];
    unsigned long long biasu = pack2(bf.x, bf.y);

    int slot   = gw >> 1;
    int nSlots = (gridDim.x * blockDim.x / 32) >> 1;

    for (int e = slot; e < nEdges; e += nSlots) {
        int src = srcArr[e];
        int dst = dstArr[e];
        const float4* ear = (const float4*)(ea + (size_t)e * 32);
        unsigned long long acc0 = biasu, acc1 = 0ull;
#pragma unroll
        for (int q = 0; q < 8; q++) {
            float4 v = ear[q];
            acc0 = fma2(pack2(v.x, v.x), wreg[4 * q + 0], acc0);
            acc1 = fma2(pack2(v.y, v.y), wreg[4 * q + 1], acc1);
            acc0 = fma2(pack2(v.z, v.z), wreg[4 * q + 2], acc0);
            acc1 = fma2(pack2(v.w, v.w), wreg[4 * q + 3], acc1);
        }
        float2 a0 = unpack2(acc0), a1 = unpack2(acc1);
        float2 xr = *(const float2*)&x[(size_t)src * 128 + c0];
        float m0 = fmaxf(a0.x + a1.x + xr.x, 0.f);
        float m1 = fmaxf(a0.y + a1.y + xr.y, 0.f);
        red2(agg + (size_t)dst * 128 + c0, m0, m1);
    }
}

// ---------- Fused node kernel: h0 = x+agg; t = relu(h0@W1+b1); h2 = t@W2+b2; LN; relu(h2+x) ----------
// Block = 64 nodes, 256 threads. Dynamic smem layout (floats):
//   phase1: hs[64][132] @0 (8448), wc[32][256] @8448 (8192)
//   phase2: ts[64][260] @0 (16640, exact overlay of hs+wc), wc2[32][132] @16640 (4224)
//   epi   : h2s[64][132] @0
#define MLP_SMEM ((16640 + 4224) * 4)

__global__ void __launch_bounds__(256, 2) mlp_kernel(
    const float* __restrict__ xin, const float* __restrict__ agg,
    const float* __restrict__ W1, const float* __restrict__ b1,
    const float* __restrict__ W2, const float* __restrict__ b2,
    const float* __restrict__ lnw, const float* __restrict__ lnb,
    float* __restrict__ xout, int nNodes)
{
    extern __shared__ float sm[];
    float* hs  = sm;            // [64][132]
    float* wc  = sm + 8448;     // [32][256]
    float* ts  = sm;            // [64][260] overlay
    float* wc2 = sm + 16640;    // [32][132]
    float* h2s = sm;            // [64][132] overlay

    int tid = threadIdx.x;
    int tx = tid & 15, ty = tid >> 4;
    int m0 = blockIdx.x * 64;

    // stage h0 = x + agg
    {
        const float4* x4 = (const float4*)xin;
        const float4* a4 = (const float4*)agg;
#pragma unroll
        for (int it = 0; it < 8; it++) {
            int t = tid + it * 256;
            int r = t >> 5, c4 = t & 31;
            int gn = m0 + r;
            float4 v = make_float4(0.f, 0.f, 0.f, 0.f);
            if (gn < nNodes) {
                float4 a = x4[(size_t)gn * 32 + c4];
                float4 g = a4[(size_t)gn * 32 + c4];
                v = make_float4(a.x + g.x, a.y + g.y, a.z + g.z, a.w + g.w);
            }
            *(float4*)&hs[r * 132 + c4 * 4] = v;
        }
    }

    // ---- phase 1: t = relu(h0 @ W1 + b1), thread tile 4 nodes x 16 units ----
    unsigned long long acc[4][4][2];
#pragma unroll
    for (int i = 0; i < 4; i++)
#pragma unroll
        for (int j = 0; j < 4; j++) { acc[i][j][0] = 0ull; acc[i][j][1] = 0ull; }

    for (int kc = 0; kc < 4; kc++) {
#pragma unroll
        for (int it = 0; it < 8; it++) {
            int t = tid + it * 256;           // 0..2047
            int kk = t >> 6, c4 = t & 63;
            *(float4*)&wc[kk * 256 + c4 * 4] =
                *(const float4*)&W1[(size_t)(kc * 32 + kk) * 256 + c4 * 4];
        }
        __syncthreads();
#pragma unroll 8
        for (int kk = 0; kk < 32; kk++) {
            int k = kc * 32 + kk;
            unsigned long long aa[4];
#pragma unroll
            for (int i = 0; i < 4; i++) {
                float a = hs[(ty * 4 + i) * 132 + k];
                aa[i] = pack2(a, a);
            }
#pragma unroll
            for (int j = 0; j < 4; j++) {
                ulonglong2 w = *(const ulonglong2*)&wc[kk * 256 + j * 64 + tx * 4];
#pragma unroll
                for (int i = 0; i < 4; i++) {
                    acc[i][j][0] = fma2(aa[i], w.x, acc[i][j][0]);
                    acc[i][j][1] = fma2(aa[i], w.y, acc[i][j][1]);
                }
            }
        }
        __syncthreads();
    }

    // bias + relu, write t into ts (overlays hs+wc; all reads done at last sync)
#pragma unroll
    for (int j = 0; j < 4; j++) {
        float4 bv = *(const float4*)&b1[j * 64 + tx * 4];
#pragma unroll
        for (int i = 0; i < 4; i++) {
            float2 p0 = unpack2(acc[i][j][0]);
            float2 p1 = unpack2(acc[i][j][1]);
            float4 o = make_float4(fmaxf(p0.x + bv.x, 0.f), fmaxf(p0.y + bv.y, 0.f),
                                   fmaxf(p1.x + bv.z, 0.f), fmaxf(p1.y + bv.w, 0.f));
            *(float4*)&ts[(ty * 4 + i) * 260 + j * 64 + tx * 4] = o;
        }
    }
    __syncthreads();

    // ---- phase 2: h2 = t @ W2 + b2, thread tile 4 nodes x 8 outputs ----
    unsigned long long acc2[4][2][2];
#pragma unroll
    for (int i = 0; i < 4; i++)
#pragma unroll
        for (int j = 0; j < 2; j++) { acc2[i][j][0] = 0ull; acc2[i][j][1] = 0ull; }

    for (int kc = 0; kc < 8; kc++) {
#pragma unroll
        for (int it = 0; it < 4; it++) {
            int t = tid + it * 256;           // 0..1023
            int kk = t >> 5, c4 = t & 31;
            *(float4*)&wc2[kk * 132 + c4 * 4] =
                *(const float4*)&W2[(size_t)(kc * 32 + kk) * 128 + c4 * 4];
        }
        __syncthreads();
#pragma unroll 8
        for (int kk = 0; kk < 32; kk++) {
            int k = kc * 32 + kk;
            unsigned long long aa[4];
#pragma unroll
            for (int i = 0; i < 4; i++) {
                float a = ts[(ty * 4 + i) * 260 + k];
                aa[i] = pack2(a, a);
            }
#pragma unroll
            for (int j2 = 0; j2 < 2; j2++) {
                ulonglong2 w = *(const ulonglong2*)&wc2[kk * 132 + j2 * 64 + tx * 4];
#pragma unroll
                for (int i = 0; i < 4; i++) {
                    acc2[i][j2][0] = fma2(aa[i], w.x, acc2[i][j2][0]);
                    acc2[i][j2][1] = fma2(aa[i], w.y, acc2[i][j2][1]);
                }
            }
        }
        __syncthreads();
    }

    // write h2 + b2 into h2s (overlays ts)
#pragma unroll
    for (int j2 = 0; j2 < 2; j2++) {
        float4 bv = *(const float4*)&b2[j2 * 64 + tx * 4];
#pragma unroll
        for (int i = 0; i < 4; i++) {
            float2 p0 = unpack2(acc2[i][j2][0]);
            float2 p1 = unpack2(acc2[i][j2][1]);
            float4 o = make_float4(p0.x + bv.x, p0.y + bv.y, p1.x + bv.z, p1.y + bv.w);
            *(float4*)&h2s[(ty * 4 + i) * 132 + j2 * 64 + tx * 4] = o;
        }
    }
    __syncthreads();

    // ---- LayerNorm + residual + relu: 4 threads per node (q = 32-ch quarter) ----
    {
        int n = tid >> 2, q = tid & 3;
        int gn = m0 + n;
        const float* row = &h2s[n * 132 + q * 32];
        float4 v[8];
        float s = 0.f;
#pragma unroll
        for (int m = 0; m < 8; m++) {
            v[m] = *(const float4*)&row[m * 4];
            s += v[m].x + v[m].y + v[m].z + v[m].w;
        }
        s += __shfl_xor_sync(0xffffffffu, s, 1);
        s += __shfl_xor_sync(0xffffffffu, s, 2);
        float mu = s * (1.0f / 128.0f);
        float sq = 0.f;
#pragma unroll
        for (int m = 0; m < 8; m++) {
            float dx = v[m].x - mu, dy = v[m].y - mu, dz = v[m].z - mu, dw = v[m].w - mu;
            sq += dx * dx + dy * dy + dz * dz + dw * dw;
        }
        sq += __shfl_xor_sync(0xffffffffu, sq, 1);
        sq += __shfl_xor_sync(0xffffffffu, sq, 2);
        float inv = rsqrtf(sq * (1.0f / 128.0f) + 1e-5f);
        if (gn < nNodes) {
            const float4* lw4 = (const float4*)lnw;
            const float4* lb4 = (const float4*)lnb;
#pragma unroll
            for (int m = 0; m < 8; m++) {
                int c4 = q * 8 + m;
                float4 w = lw4[c4], b = lb4[c4];
                float4 xr = *(const float4*)&xin[(size_t)gn * 128 + c4 * 4];
                float4 o;
                o.x = fmaxf((v[m].x - mu) * inv * w.x + b.x + xr.x, 0.f);
                o.y = fmaxf((v[m].y - mu) * inv * w.y + b.y + xr.y, 0.f);
                o.z = fmaxf((v[m].z - mu) * inv * w.z + b.z + xr.z, 0.f);
                o.w = fmaxf((v[m].w - mu) * inv * w.w + b.w + xr.w, 0.f);
                *(float4*)&xout[(size_t)gn * 128 + c4 * 4] = o;
            }
        }
    }
}

// ---------- Output projection: out = x @ Wout + bout  ([100k,128]@[128,64]) ----------
__global__ void __launch_bounds__(256) proj_kernel(
    const float* __restrict__ x, const float* __restrict__ Wout,
    const float* __restrict__ bout, float* __restrict__ out, int nNodes)
{
    __shared__ float xs[64 * 132];
    __shared__ float ws[32 * 64];
    int tid = threadIdx.x, tx = tid & 15, ty = tid >> 4;
    int m0 = blockIdx.x * 64;

#pragma unroll
    for (int it = 0; it < 8; it++) {
        int t = tid + it * 256;
        int r = t >> 5, c4 = t & 31;
        int gn = m0 + r;
        float4 v = make_float4(0.f, 0.f, 0.f, 0.f);
        if (gn < nNodes) v = ((const float4*)x)[(size_t)gn * 32 + c4];
        *(float4*)&xs[r * 132 + c4 * 4] = v;
    }

    unsigned long long acc[4][2];
#pragma unroll
    for (int i = 0; i < 4; i++) { acc[i][0] = 0ull; acc[i][1] = 0ull; }

    for (int kc = 0; kc < 4; kc++) {
#pragma unroll
        for (int it = 0; it < 2; it++) {
            int t = tid + it * 256;          // 0..511
            int kk = t >> 4, c4 = t & 15;
            *(float4*)&ws[kk * 64 + c4 * 4] =
                *(const float4*)&Wout[(size_t)(kc * 32 + kk) * 64 + c4 * 4];
        }
        __syncthreads();
#pragma unroll 8
        for (int kk = 0; kk < 32; kk++) {
            int k = kc * 32 + kk;
            ulonglong2 w = *(const ulonglong2*)&ws[kk * 64 + tx * 4];
#pragma unroll
            for (int i = 0; i < 4; i++) {
                float a = xs[(ty * 4 + i) * 132 + k];
                unsigned long long aa = pack2(a, a);
                acc[i][0] = fma2(aa, w.x, acc[i][0]);
                acc[i][1] = fma2(aa, w.y, acc[i][1]);
            }
        }
        __syncthreads();
    }

    float4 bv = *(const float4*)&bout[tx * 4];
#pragma unroll
    for (int i = 0; i < 4; i++) {
        int gn = m0 + ty * 4 + i;
        if (gn < nNodes) {
            float2 p0 = unpack2(acc[i][0]), p1 = unpack2(acc[i][1]);
            float4 o = make_float4(p0.x + bv.x, p0.y + bv.y, p1.x + bv.z, p1.y + bv.w);
            *(float4*)&out[(size_t)gn * 64 + tx * 4] = o;
        }
    }
}

extern "C" void kernel_launch(void* const* d_in, const int* in_sizes, int n_in,
                              void* d_out, int out_size) {
    const float* x        = (const float*)d_in[0];
    const void*  ei       = (const void*)d_in[1];
    const float* ea       = (const float*)d_in[2];
    const float* We       = (const float*)d_in[3];
    const float* be       = (const float*)d_in[4];
    const float* W1       = (const float*)d_in[5];
    const float* b1       = (const float*)d_in[6];
    const float* W2       = (const float*)d_in[7];
    const float* b2       = (const float*)d_in[8];
    const float* lnw      = (const float*)d_in[9];
    const float* lnb      = (const float*)d_in[10];
    const float* Wout     = (const float*)d_in[11];
    const float* bout     = (const float*)d_in[12];
    float* out            = (float*)d_out;

    int nNodes = in_sizes[0] / CH;
    int nEdges = in_sizes[1] / 2;

    float *xb0, *xb1, *agg;
    int   *ei32;
    cudaGetSymbolAddress((void**)&xb0, g_x0);
    cudaGetSymbolAddress((void**)&xb1, g_x1);
    cudaGetSymbolAddress((void**)&agg, g_agg);
    cudaGetSymbolAddress((void**)&ei32, g_ei32);

    cudaFuncSetAttribute(mlp_kernel, cudaFuncAttributeMaxDynamicSharedMemorySize, MLP_SMEM);

    // canonicalize edge indices (handles int32 OR int64 edge_index)
    detect_kernel<<<1, 32>>>((const unsigned int*)ei);
    convert_kernel<<<256, 256>>>(ei, 2 * nEdges);

    int mlpBlocks = (nNodes + 63) / 64;
    const float* cur = x;
    for (int l = 0; l < 4; l++) {
        float* nxt = (l & 1) ? xb1 : xb0;
        cudaMemsetAsync(agg, 0, (size_t)nNodes * CH * sizeof(float), 0);
        edge_kernel<<<592, 256>>>(cur, ei32, ei32 + nEdges, ea,
                                  We + (size_t)l * 32 * CH,
                                  be + (size_t)l * CH, agg, nEdges);
        mlp_kernel<<<mlpBlocks, 256, MLP_SMEM>>>(
            cur, agg, W1 + (size_t)l * CH * 256, b1 + (size_t)l * 256,
            W2 + (size_t)l * 256 * CH, b2 + (size_t)l * CH,
            lnw + (size_t)l * CH, lnb + (size_t)l * CH, nxt, nNodes);
        cur = nxt;
    }
    proj_kernel<<<mlpBlocks, 256>>>(cur, Wout, bout, out, nNodes);
}